// round 9
// baseline (speedup 1.0000x reference)
#include <cuda_runtime.h>
#include <cuda_bf16.h>
#include <cstdint>

// Sparsemax along last dim of a [ROWS, 32000] fp32 matrix.
//
// Exact, sort-free: tau solves sum_i max(x_i - tau, 0) = 1 and tau >= rowmax-1,
// so the support lies in C = {x > rowmax - 1} (~25 elems/row, Gaussian data).
//
// Persistent CTAs (grid = #SMs, 1024 threads). Row split main(28672 floats,
// 112KB, single buffer) + head(3328 floats, 13KB, double-buffered). Main TMA
// issued at barrier A (delivered during the compute phase, as in the proven
// R6 schedule). Head TMAs are queued BEHIND the main TMA and spill into the
// next row's SMEM->reg copy window, keeping the DRAM read stream continuous
// with only a 13KB delivery trickle concurrent with the copy.
// Two block barriers per row; all warps redundantly run Michelot on the
// compacted candidate list (no broadcast barrier).

#define SMX_N        32000
#define SMX_MAIN_F4  7168           // float4 in main part (7 per thread exactly)
#define SMX_MAIN_FL  28672
#define SMX_MAIN_B   114688
#define SMX_HEAD_F4  832
#define SMX_HEAD_FL  3328
#define SMX_HEAD_B   13312
#define SMX_THREADS  1024
#define SMX_NEG      (-3.0e38f)
#define SMX_CAP      1024

__device__ __forceinline__ uint32_t smx_smem_u32(const void* p) {
    uint32_t a;
    asm("{ .reg .u64 t; cvta.to.shared.u64 t, %1; cvt.u32.u64 %0, t; }"
        : "=r"(a) : "l"(p));
    return a;
}
__device__ __forceinline__ void smx_mbar_init(uint32_t mbar, uint32_t count) {
    asm volatile("mbarrier.init.shared.b64 [%0], %1;" :: "r"(mbar), "r"(count) : "memory");
}
__device__ __forceinline__ void smx_expect_tx(uint32_t mbar, uint32_t bytes) {
    asm volatile("mbarrier.arrive.expect_tx.shared.b64 _, [%0], %1;"
                 :: "r"(mbar), "r"(bytes) : "memory");
}
__device__ __forceinline__ void smx_bulk_g2s(uint32_t dst, const void* src,
                                             uint32_t bytes, uint32_t mbar) {
    asm volatile(
        "cp.async.bulk.shared::cta.global.mbarrier::complete_tx::bytes [%0], [%1], %2, [%3];"
        :: "r"(dst), "l"(src), "r"(bytes), "r"(mbar) : "memory");
}
__device__ __forceinline__ void smx_mbar_wait(uint32_t mbar, uint32_t parity) {
    asm volatile(
        "{\n\t"
        ".reg .pred P;\n\t"
        "SMXW%=:\n\t"
        "mbarrier.try_wait.parity.acquire.cta.shared::cta.b64 P, [%0], %1, 0x989680;\n\t"
        "@P bra SMXD%=;\n\t"
        "bra SMXW%=;\n\t"
        "SMXD%=:\n\t"
        "}"
        :: "r"(mbar), "r"(parity) : "memory");
}
__device__ __forceinline__ void smx_fence_async() {
    asm volatile("fence.proxy.async.shared::cta;" ::: "memory");
}

// order-preserving float<->uint for shared atomicMax
__device__ __forceinline__ unsigned smx_enc(float f) {
    unsigned b = __float_as_uint(f);
    return (b & 0x80000000u) ? ~b : (b | 0x80000000u);
}
__device__ __forceinline__ float smx_dec(unsigned u) {
    return (u & 0x80000000u) ? __uint_as_float(u & 0x7fffffffu)
                             : __uint_as_float(~u);
}

// smem: [0,28672) main | [28672,32000) head0 | [32000,35328) head1
extern __shared__ float smx_buf[];
#define SMX_SMEM_TOTAL ((SMX_MAIN_FL + 2 * SMX_HEAD_FL) * 4)

__global__ __launch_bounds__(SMX_THREADS, 1)
void sparsemax_kernel(const float* __restrict__ x, float* __restrict__ y, int rows) {
    const int t    = threadIdx.x;
    const int lane = t & 31;
    const int stride = gridDim.x;

    __shared__ __align__(8) uint64_t s_mbarM, s_mbarH[2];
    __shared__ unsigned s_maxbits[2];
    __shared__ int      s_cnt[2];
    __shared__ float    s_red[2][2];          // fallback accumulators
    __shared__ float    s_cand[2][SMX_CAP];

    const uint32_t mbarM  = smx_smem_u32(&s_mbarM);
    const uint32_t mbarH0 = smx_smem_u32(&s_mbarH[0]);
    const uint32_t mbarH1 = smx_smem_u32(&s_mbarH[1]);
    const uint32_t bufM   = smx_smem_u32(smx_buf);
    const uint32_t bufH0  = smx_smem_u32(smx_buf + SMX_MAIN_FL);
    const uint32_t bufH1  = smx_smem_u32(smx_buf + SMX_MAIN_FL + SMX_HEAD_FL);

    if (t == 0) {
        smx_mbar_init(mbarM, 1);
        smx_mbar_init(mbarH0, 1);
        smx_mbar_init(mbarH1, 1);
        s_maxbits[0] = 0u;  s_cnt[0] = 0;
        s_maxbits[1] = 0u;  s_cnt[1] = 0;
    }
    __syncthreads();

    const int row0 = blockIdx.x;
    if (row0 >= rows) return;

    if (t == 0) {
        const float* rp = x + (size_t)row0 * SMX_N;
        smx_expect_tx(mbarM, SMX_MAIN_B);
        smx_bulk_g2s(bufM, rp, SMX_MAIN_B, mbarM);
        smx_expect_tx(mbarH0, SMX_HEAD_B);
        smx_bulk_g2s(bufH0, rp + SMX_MAIN_FL, SMX_HEAD_B, mbarH0);
        if (row0 + stride < rows) {
            smx_expect_tx(mbarH1, SMX_HEAD_B);
            smx_bulk_g2s(bufH1, x + (size_t)(row0 + stride) * SMX_N + SMX_MAIN_FL,
                         SMX_HEAD_B, mbarH1);
        }
    }

    uint32_t pm = 0;            // main mbar phase (flips every row)
    uint32_t ph[2] = {0, 0};    // head mbar phases (flip every other row)
    unsigned p = 0;             // row-parity for scratch slots
    int k = 0;

    for (int r = row0; r < rows; r += stride, k++) {
        const int hb = k & 1;
        const uint32_t mbarH = hb ? mbarH1 : mbarH0;
        const uint32_t bufH  = hb ? bufH1 : bufH0;

        smx_mbar_wait(mbarM, pm);
        smx_mbar_wait(mbarH, ph[hb]);

        // ---- SMEM -> registers with fused running max ----
        float4 v[8];
        float m = SMX_NEG;
        {
            const float4* s4 = reinterpret_cast<const float4*>(smx_buf);
            #pragma unroll
            for (int i = 0; i < 7; i++) {            // main: no bounds checks
                v[i] = s4[i * SMX_THREADS + t];
                m = fmaxf(m, fmaxf(fmaxf(v[i].x, v[i].y), fmaxf(v[i].z, v[i].w)));
            }
            const float4* h4 = reinterpret_cast<const float4*>(
                smx_buf + SMX_MAIN_FL + (hb ? SMX_HEAD_FL : 0));
            if (t < SMX_HEAD_F4) {
                v[7] = h4[t];
                m = fmaxf(m, fmaxf(fmaxf(v[7].x, v[7].y), fmaxf(v[7].z, v[7].w)));
            } else {
                v[7] = make_float4(SMX_NEG, SMX_NEG, SMX_NEG, SMX_NEG);
            }
        }

        // warp max-reduce + shared atomicMax (pre-barrier)
        #pragma unroll
        for (int o = 16; o; o >>= 1)
            m = fmaxf(m, __shfl_xor_sync(0xffffffffu, m, o));
        if (lane == 0) atomicMax(&s_maxbits[p], smx_enc(m));

        __syncthreads();   // barrier A: buffer reads done + rowmax published

        // t0: release buffers; queue main(r+1) then head(r+2) — the head TMA
        // trails the main one and spills into the next copy window.
        if (t == 0) {
            smx_fence_async();
            if (r + stride < rows) {
                smx_expect_tx(mbarM, SMX_MAIN_B);
                smx_bulk_g2s(bufM, x + (size_t)(r + stride) * SMX_N, SMX_MAIN_B, mbarM);
            }
            if (r + 2 * stride < rows) {
                smx_expect_tx(mbarH, SMX_HEAD_B);
                smx_bulk_g2s(bufH, x + (size_t)(r + 2 * stride) * SMX_N + SMX_MAIN_FL,
                             SMX_HEAD_B, mbarH);
            }
        }

        const float thr = smx_dec(s_maxbits[p]) - 1.0f;   // tau >= thr always
        if (t == 1) { s_maxbits[p ^ 1] = 0u; s_cnt[p ^ 1] = 0; }

        // ---- compact candidates {x > thr} into s_cand[p] ----
        #pragma unroll
        for (int i = 0; i < 8; i++) {
            const float a0 = v[i].x, a1 = v[i].y, a2 = v[i].z, a3 = v[i].w;
            if (a0 > thr) { int q = atomicAdd(&s_cnt[p], 1); if (q < SMX_CAP) s_cand[p][q] = a0; }
            if (a1 > thr) { int q = atomicAdd(&s_cnt[p], 1); if (q < SMX_CAP) s_cand[p][q] = a1; }
            if (a2 > thr) { int q = atomicAdd(&s_cnt[p], 1); if (q < SMX_CAP) s_cand[p][q] = a2; }
            if (a3 > thr) { int q = atomicAdd(&s_cnt[p], 1); if (q < SMX_CAP) s_cand[p][q] = a3; }
        }
        __syncthreads();   // barrier B: candidate list complete
        const int cnt = s_cnt[p];

        float tau;
        if (cnt <= SMX_CAP) {
            // ---- every warp redundantly: Michelot on the candidate list ----
            tau = thr;
            float prevc = -1.0f;
            #pragma unroll 1
            for (int it = 0; it < 64; it++) {
                float s = 0.0f, c = 0.0f;
                for (int j = lane; j < cnt; j += 32) {
                    const float z = s_cand[p][j];
                    if (z > tau) { s += z; c += 1.0f; }
                }
                #pragma unroll
                for (int o = 16; o; o >>= 1) {
                    s += __shfl_xor_sync(0xffffffffu, s, o);
                    c += __shfl_xor_sync(0xffffffffu, c, o);
                }
                tau = (s - 1.0f) / c;
                if (c == prevc) break;        // fixed point: exact tau
                prevc = c;
            }
        } else {
            // ---- fallback: full-row Michelot via shared atomics (rare) ----
            if (t == 0) { s_red[0][0] = 0.f; s_red[0][1] = 0.f;
                          s_red[1][0] = 0.f; s_red[1][1] = 0.f; }
            __syncthreads();
            tau = thr;
            float prevc = -1.0f;
            unsigned q = 0;
            #pragma unroll 1
            for (int it = 0; it < 64; it++) {
                float s = 0.0f, c = 0.0f;
                #pragma unroll
                for (int i = 0; i < 8; i++) {
                    if (v[i].x > tau) { s += v[i].x; c += 1.0f; }
                    if (v[i].y > tau) { s += v[i].y; c += 1.0f; }
                    if (v[i].z > tau) { s += v[i].z; c += 1.0f; }
                    if (v[i].w > tau) { s += v[i].w; c += 1.0f; }
                }
                #pragma unroll
                for (int o = 16; o; o >>= 1) {
                    s += __shfl_xor_sync(0xffffffffu, s, o);
                    c += __shfl_xor_sync(0xffffffffu, c, o);
                }
                if (lane == 0) { atomicAdd(&s_red[q][0], s); atomicAdd(&s_red[q][1], c); }
                if (t == 0)    { s_red[q ^ 1][0] = 0.f; s_red[q ^ 1][1] = 0.f; }
                __syncthreads();
                const float S = s_red[q][0], C = s_red[q][1];
                __syncthreads();
                tau = (S - 1.0f) / C;
                if (C == prevc) break;
                prevc = C;
                q ^= 1;
            }
        }

        // ---- output: max(x - tau, 0), coalesced, evict-first ----
        float4* __restrict__ yr = reinterpret_cast<float4*>(y + (size_t)r * SMX_N);
        #pragma unroll
        for (int i = 0; i < 7; i++) {
            float4 o;
            o.x = fmaxf(v[i].x - tau, 0.0f);
            o.y = fmaxf(v[i].y - tau, 0.0f);
            o.z = fmaxf(v[i].z - tau, 0.0f);
            o.w = fmaxf(v[i].w - tau, 0.0f);
            __stcs(&yr[i * SMX_THREADS + t], o);
        }
        if (t < SMX_HEAD_F4) {
            float4 o;
            o.x = fmaxf(v[7].x - tau, 0.0f);
            o.y = fmaxf(v[7].y - tau, 0.0f);
            o.z = fmaxf(v[7].z - tau, 0.0f);
            o.w = fmaxf(v[7].w - tau, 0.0f);
            __stcs(&yr[SMX_MAIN_F4 + t], o);
        }

        pm ^= 1u;
        ph[hb] ^= 1u;
        p ^= 1u;
    }
}

extern "C" void kernel_launch(void* const* d_in, const int* in_sizes, int n_in,
                              void* d_out, int out_size) {
    const float* x = (const float*)d_in[0];
    float* y = (float*)d_out;
    const int rows = in_sizes[0] / SMX_N;

    int dev = 0, sms = 148;
    cudaGetDevice(&dev);
    cudaDeviceGetAttribute(&sms, cudaDevAttrMultiProcessorCount, dev);

    static bool attr_done = false;
    if (!attr_done) {
        cudaFuncSetAttribute(sparsemax_kernel,
                             cudaFuncAttributeMaxDynamicSharedMemorySize,
                             SMX_SMEM_TOTAL);
        attr_done = true;
    }

    int grid = rows < sms ? rows : sms;
    sparsemax_kernel<<<grid, SMX_THREADS, SMX_SMEM_TOTAL>>>(x, y, rows);
}